// round 2
// baseline (speedup 1.0000x reference)
#include <cuda_runtime.h>
#include <cstdint>

#define N_TOK   2048
#define D_IN    2048
#define D_OUT   2048
#define NEXP    8
#define BM      128
#define BN      128
#define BK      32
#define ASTRIDE 36          // BK + 4 pad: conflict-free fragment reads
#define NTHREADS 256
#define MAX_MTILES 40       // sum_e ceil(M_e/BM) <= 4096/128 + 8 = 40

__global__ void zero_out_kernel(float4* __restrict__ out) {
    int i = blockIdx.x * blockDim.x + threadIdx.x;
    out[i] = make_float4(0.f, 0.f, 0.f, 0.f);
}

__device__ __forceinline__ uint32_t f2tf32(float f) {
    uint32_t u;
    asm("cvt.rna.tf32.f32 %0, %1;" : "=r"(u) : "f"(f));
    return u;
}

__global__ __launch_bounds__(NTHREADS)
void moe_gemm_kernel(const float* __restrict__ inputs,
                     const float* __restrict__ weight,
                     const int*   __restrict__ ssi,     // sorted_scattered_idxs [4096]
                     const int*   __restrict__ offs,    // expert_offsets (cumsum) [8]
                     const float* __restrict__ gates,   // flat [4096]
                     float*       __restrict__ out)
{
    __shared__ uint32_t As[BM][ASTRIDE];
    __shared__ uint32_t Bs[BN][ASTRIDE];
    __shared__ int   toks[BM];
    __shared__ float gts[BM];

    // ---- on-device grouped-GEMM tile scheduler ----
    int y = blockIdx.y;
    int e = -1, t = 0, segStart = 0, segLen = 0, cum = 0;
    #pragma unroll
    for (int i = 0; i < NEXP; i++) {
        int s   = (i == 0) ? 0 : offs[i - 1];
        int en  = offs[i];
        int len = en - s;
        int nt  = (len + BM - 1) / BM;
        if (e < 0 && y < cum + nt) { e = i; t = y - cum; segStart = s; segLen = len; }
        cum += nt;
    }
    if (e < 0) return;

    int p0 = segStart + t * BM;
    int rowsValid = segLen - t * BM;
    if (rowsValid > BM) rowsValid = BM;

    int tid = threadIdx.x;
    if (tid < BM) {
        if (tid < rowsValid) {
            int j = ssi[p0 + tid];
            toks[tid] = j >> 1;          // token = j / TOPK (TOPK = 2)
            gts[tid]  = gates[j];        // gates flat [N*TOPK]
        } else {
            toks[tid] = 0;               // safe dummy row (never stored)
            gts[tid]  = 0.f;
        }
    }
    __syncthreads();

    const float* W = weight + (size_t)e * D_OUT * D_IN + (size_t)(blockIdx.x * BN) * D_IN;

    int lane = tid & 31, warp = tid >> 5;
    int warpM = warp >> 1;   // 0..3 -> 32 rows each
    int warpN = warp & 1;    // 0..1 -> 64 cols each
    int g  = lane >> 2;      // groupID 0..7
    int t4 = lane & 3;       // tid-in-group 0..3

    float c[2][8][4];
    #pragma unroll
    for (int m = 0; m < 2; m++)
        #pragma unroll
        for (int n = 0; n < 8; n++)
            #pragma unroll
            for (int q = 0; q < 4; q++) c[m][n][q] = 0.f;

    int lr = tid >> 3;   // 0..31: smem row base for loading
    int lg = tid & 7;    // 0..7 : 16B group within a 32-float row

    for (int kb = 0; kb < D_IN; kb += BK) {
        // ---- load A tile (gathered rows of inputs), tf32-rounded ----
        #pragma unroll
        for (int i = 0; i < 4; i++) {
            int r = lr + i * 32;
            const float4 v = *reinterpret_cast<const float4*>(
                inputs + (size_t)toks[r] * D_IN + kb + lg * 4);
            As[r][lg * 4 + 0] = f2tf32(v.x);
            As[r][lg * 4 + 1] = f2tf32(v.y);
            As[r][lg * 4 + 2] = f2tf32(v.z);
            As[r][lg * 4 + 3] = f2tf32(v.w);
        }
        // ---- load B tile (weight rows = output cols), tf32-rounded ----
        #pragma unroll
        for (int i = 0; i < 4; i++) {
            int r = lr + i * 32;
            const float4 v = *reinterpret_cast<const float4*>(
                W + (size_t)r * D_IN + kb + lg * 4);
            Bs[r][lg * 4 + 0] = f2tf32(v.x);
            Bs[r][lg * 4 + 1] = f2tf32(v.y);
            Bs[r][lg * 4 + 2] = f2tf32(v.z);
            Bs[r][lg * 4 + 3] = f2tf32(v.w);
        }
        __syncthreads();

        #pragma unroll
        for (int kk = 0; kk < BK; kk += 8) {
            uint32_t a[2][4], b[8][2];
            #pragma unroll
            for (int m = 0; m < 2; m++) {
                int r0 = warpM * 32 + m * 16;
                // PTX m16n8k8 A-fragment order:
                // a0=(g,t4) a1=(g+8,t4) a2=(g,t4+4) a3=(g+8,t4+4)
                a[m][0] = As[r0 + g][kk + t4];
                a[m][1] = As[r0 + 8 + g][kk + t4];
                a[m][2] = As[r0 + g][kk + t4 + 4];
                a[m][3] = As[r0 + 8 + g][kk + t4 + 4];
            }
            #pragma unroll
            for (int n = 0; n < 8; n++) {
                int cb = warpN * 64 + n * 8 + g;
                b[n][0] = Bs[cb][kk + t4];
                b[n][1] = Bs[cb][kk + t4 + 4];
            }
            #pragma unroll
            for (int m = 0; m < 2; m++)
                #pragma unroll
                for (int n = 0; n < 8; n++) {
                    asm volatile(
                        "mma.sync.aligned.m16n8k8.row.col.f32.tf32.tf32.f32 "
                        "{%0,%1,%2,%3},{%4,%5,%6,%7},{%8,%9},{%0,%1,%2,%3};"
                        : "+f"(c[m][n][0]), "+f"(c[m][n][1]),
                          "+f"(c[m][n][2]), "+f"(c[m][n][3])
                        : "r"(a[m][0]), "r"(a[m][1]), "r"(a[m][2]), "r"(a[m][3]),
                          "r"(b[n][0]), "r"(b[n][1]));
                }
        }
        __syncthreads();
    }

    // ---- fused gate-combine epilogue: out[token] += gate * acc ----
    int colBase = blockIdx.x * BN + warpN * 64;
    #pragma unroll
    for (int m = 0; m < 2; m++) {
        int r0 = warpM * 32 + m * 16 + g;
        int r1 = r0 + 8;
        #pragma unroll
        for (int n = 0; n < 8; n++) {
            int col = colBase + n * 8 + t4 * 2;
            if (r0 < rowsValid) {
                float w = gts[r0];
                float* o = out + (size_t)toks[r0] * D_OUT + col;
                atomicAdd(o,     w * c[m][n][0]);
                atomicAdd(o + 1, w * c[m][n][1]);
            }
            if (r1 < rowsValid) {
                float w = gts[r1];
                float* o = out + (size_t)toks[r1] * D_OUT + col;
                atomicAdd(o,     w * c[m][n][2]);
                atomicAdd(o + 1, w * c[m][n][3]);
            }
        }
    }
}

extern "C" void kernel_launch(void* const* d_in, const int* in_sizes, int n_in,
                              void* d_out, int out_size)
{
    // metadata order: inputs, weight, [k], sorted_expert_idxs, sorted_scattered_idxs,
    //                 padded_block_idxs, expert_offsets, gates
    // Index from the tail so it is invariant to whether scalar k is materialized:
    //   n_in-1: gates [4096], n_in-2: expert_offsets [8],
    //   n_in-3: padded_block_idxs [1], n_in-4: sorted_scattered_idxs [4096]
    const float* inputs = (const float*)d_in[0];
    const float* weight = (const float*)d_in[1];
    const int*   ssi    = (const int*)  d_in[n_in - 4];
    const int*   offs   = (const int*)  d_in[n_in - 2];
    const float* gates  = (const float*)d_in[n_in - 1];
    float* out = (float*)d_out;

    // zero the (poisoned) output, then grouped GEMM with fused combine
    zero_out_kernel<<<(N_TOK * D_OUT / 4) / 256, 256>>>((float4*)out);
    dim3 grid(D_OUT / BN, MAX_MTILES);
    moe_gemm_kernel<<<grid, NTHREADS>>>(inputs, weight, ssi, offs, gates, out);
}

// round 3
// speedup vs baseline: 1.6460x; 1.6460x over previous
#include <cuda_runtime.h>
#include <cstdint>

#define N_TOK   2048
#define D_IN    2048
#define D_OUT   2048
#define NEXP    8
#define BM      128
#define BN      128
#define BK      32
#define ASTRIDE 36          // BK + 4 pad: conflict-free fragment reads, rows stay 16B-aligned (144B)
#define NTHREADS 256
#define MAX_MTILES 40
#define NKTILES (D_IN / BK)                 // 64
#define STAGE_WORDS (BM * ASTRIDE)          // per array per stage
#define SMEM_BYTES (2 * 2 * STAGE_WORDS * 4)  // 2 stages x (A+B) = 73728

__global__ void zero_out_kernel(float4* __restrict__ out) {
    int i = blockIdx.x * blockDim.x + threadIdx.x;
    out[i] = make_float4(0.f, 0.f, 0.f, 0.f);
}

__device__ __forceinline__ uint32_t f2tf32(float f) {
    uint32_t u;
    asm("cvt.rna.tf32.f32 %0, %1;" : "=r"(u) : "f"(f));
    return u;
}

__device__ __forceinline__ void cpasync16(uint32_t saddr, const void* gaddr) {
    asm volatile("cp.async.cg.shared.global [%0], [%1], 16;" :: "r"(saddr), "l"(gaddr));
}

extern __shared__ uint32_t dynsmem[];
#define AS(s, r, c) dynsmem[(s) * STAGE_WORDS + (r) * ASTRIDE + (c)]
#define BS(s, r, c) dynsmem[2 * STAGE_WORDS + (s) * STAGE_WORDS + (r) * ASTRIDE + (c)]

__global__ __launch_bounds__(NTHREADS, 2)
void moe_gemm_kernel(const float* __restrict__ inputs,
                     const float* __restrict__ weight,
                     const int*   __restrict__ ssi,
                     const int*   __restrict__ offs,
                     const float* __restrict__ gates,
                     float*       __restrict__ out)
{
    __shared__ int   toks[BM];
    __shared__ float gts[BM];

    // ---- on-device grouped-GEMM tile scheduler ----
    int y = blockIdx.y;
    int e = -1, t = 0, segStart = 0, segLen = 0, cum = 0;
    #pragma unroll
    for (int i = 0; i < NEXP; i++) {
        int s   = (i == 0) ? 0 : offs[i - 1];
        int en  = offs[i];
        int len = en - s;
        int nt  = (len + BM - 1) / BM;
        if (e < 0 && y < cum + nt) { e = i; t = y - cum; segStart = s; segLen = len; }
        cum += nt;
    }
    if (e < 0) return;

    int p0 = segStart + t * BM;
    int rowsValid = segLen - t * BM;
    if (rowsValid > BM) rowsValid = BM;

    int tid = threadIdx.x;
    if (tid < BM) {
        if (tid < rowsValid) {
            int j = ssi[p0 + tid];
            toks[tid] = j >> 1;
            gts[tid]  = gates[j];
        } else {
            toks[tid] = 0;
            gts[tid]  = 0.f;
        }
    }
    __syncthreads();

    const float* W = weight + (size_t)e * D_OUT * D_IN + (size_t)(blockIdx.x * BN) * D_IN;

    int lane = tid & 31, warp = tid >> 5;
    int warpM = warp >> 1;
    int warpN = warp & 1;
    int g  = lane >> 2;
    int t4 = lane & 3;

    int lr = tid >> 3;   // 0..31 row base for async loads
    int lg = tid & 7;    // 16B group within a 32-float row

    // per-thread gmem row pointers for the 4 A rows / 4 B rows this thread loads
    const float* aptr[4];
    const float* bptr[4];
    #pragma unroll
    for (int i = 0; i < 4; i++) {
        int r = lr + i * 32;
        aptr[i] = inputs + (size_t)toks[r] * D_IN + lg * 4;
        bptr[i] = W + (size_t)r * D_IN + lg * 4;
    }

    float c[2][8][4];
    #pragma unroll
    for (int m = 0; m < 2; m++)
        #pragma unroll
        for (int n = 0; n < 8; n++)
            #pragma unroll
            for (int q = 0; q < 4; q++) c[m][n][q] = 0.f;

    // ---- prologue: stage 0 ----
    #pragma unroll
    for (int i = 0; i < 4; i++) {
        int r = lr + i * 32;
        cpasync16((uint32_t)__cvta_generic_to_shared(&AS(0, r, lg * 4)), aptr[i]);
        cpasync16((uint32_t)__cvta_generic_to_shared(&BS(0, r, lg * 4)), bptr[i]);
    }
    asm volatile("cp.async.commit_group;");

    for (int kt = 0; kt < NKTILES; kt++) {
        int buf = kt & 1;
        if (kt + 1 < NKTILES) {
            int nbuf = buf ^ 1;
            int koff = (kt + 1) * BK;
            #pragma unroll
            for (int i = 0; i < 4; i++) {
                int r = lr + i * 32;
                cpasync16((uint32_t)__cvta_generic_to_shared(&AS(nbuf, r, lg * 4)), aptr[i] + koff);
                cpasync16((uint32_t)__cvta_generic_to_shared(&BS(nbuf, r, lg * 4)), bptr[i] + koff);
            }
            asm volatile("cp.async.commit_group;");
            asm volatile("cp.async.wait_group 1;");
        } else {
            asm volatile("cp.async.wait_group 0;");
        }
        __syncthreads();

        #pragma unroll
        for (int kk = 0; kk < BK; kk += 8) {
            uint32_t a[2][4], b[8][2];
            #pragma unroll
            for (int m = 0; m < 2; m++) {
                int r0 = warpM * 32 + m * 16;
                a[m][0] = f2tf32(__uint_as_float(AS(buf, r0 + g,     kk + t4)));
                a[m][1] = f2tf32(__uint_as_float(AS(buf, r0 + 8 + g, kk + t4)));
                a[m][2] = f2tf32(__uint_as_float(AS(buf, r0 + g,     kk + t4 + 4)));
                a[m][3] = f2tf32(__uint_as_float(AS(buf, r0 + 8 + g, kk + t4 + 4)));
            }
            #pragma unroll
            for (int n = 0; n < 8; n++) {
                int cb = warpN * 64 + n * 8 + g;
                b[n][0] = f2tf32(__uint_as_float(BS(buf, cb, kk + t4)));
                b[n][1] = f2tf32(__uint_as_float(BS(buf, cb, kk + t4 + 4)));
            }
            #pragma unroll
            for (int m = 0; m < 2; m++)
                #pragma unroll
                for (int n = 0; n < 8; n++) {
                    asm volatile(
                        "mma.sync.aligned.m16n8k8.row.col.f32.tf32.tf32.f32 "
                        "{%0,%1,%2,%3},{%4,%5,%6,%7},{%8,%9},{%0,%1,%2,%3};"
                        : "+f"(c[m][n][0]), "+f"(c[m][n][1]),
                          "+f"(c[m][n][2]), "+f"(c[m][n][3])
                        : "r"(a[m][0]), "r"(a[m][1]), "r"(a[m][2]), "r"(a[m][3]),
                          "r"(b[n][0]), "r"(b[n][1]));
                }
        }
        __syncthreads();
    }

    // ---- fused gate-combine epilogue: out[token] += gate * acc ----
    int colBase = blockIdx.x * BN + warpN * 64;
    #pragma unroll
    for (int m = 0; m < 2; m++) {
        int r0 = warpM * 32 + m * 16 + g;
        int r1 = r0 + 8;
        #pragma unroll
        for (int n = 0; n < 8; n++) {
            int col = colBase + n * 8 + t4 * 2;
            if (r0 < rowsValid) {
                float w = gts[r0];
                float* o = out + (size_t)toks[r0] * D_OUT + col;
                atomicAdd(o,     w * c[m][n][0]);
                atomicAdd(o + 1, w * c[m][n][1]);
            }
            if (r1 < rowsValid) {
                float w = gts[r1];
                float* o = out + (size_t)toks[r1] * D_OUT + col;
                atomicAdd(o,     w * c[m][n][2]);
                atomicAdd(o + 1, w * c[m][n][3]);
            }
        }
    }
}

extern "C" void kernel_launch(void* const* d_in, const int* in_sizes, int n_in,
                              void* d_out, int out_size)
{
    const float* inputs = (const float*)d_in[0];
    const float* weight = (const float*)d_in[1];
    const int*   ssi    = (const int*)  d_in[n_in - 4];
    const int*   offs   = (const int*)  d_in[n_in - 2];
    const float* gates  = (const float*)d_in[n_in - 1];
    float* out = (float*)d_out;

    // idempotent; host-side only, not enqueued -> capture-safe
    cudaFuncSetAttribute(moe_gemm_kernel,
                         cudaFuncAttributeMaxDynamicSharedMemorySize, SMEM_BYTES);

    zero_out_kernel<<<(N_TOK * D_OUT / 4) / 256, 256>>>((float4*)out);
    dim3 grid(D_OUT / BN, MAX_MTILES);
    moe_gemm_kernel<<<grid, NTHREADS, SMEM_BYTES>>>(inputs, weight, ssi, offs, gates, out);
}

// round 6
// speedup vs baseline: 1.7533x; 1.0652x over previous
#include <cuda_runtime.h>
#include <cstdint>

#define N_TOK   2048
#define D_IN    2048
#define D_OUT   2048
#define NEXP    8
#define BM      128
#define BN      128
#define BK      32
#define ASTRIDE 36          // BK + 4 pad: conflict-free fragment reads, rows 16B-aligned
#define NTHREADS 256
#define MAX_MTILES 40
#define NKTILES (D_IN / BK)                 // 64
#define NSTAGE  3
#define STAGE_WORDS (BM * ASTRIDE)
#define SMEM_BYTES (NSTAGE * 2 * STAGE_WORDS * 4)   // 110592 B; 2 CTAs = 221KB <= 228KB

__global__ void zero_out_kernel(float4* __restrict__ out) {
    int i = blockIdx.x * blockDim.x + threadIdx.x;
    out[i] = make_float4(0.f, 0.f, 0.f, 0.f);
}

__device__ __forceinline__ uint32_t f2tf32(uint32_t fbits) {
    uint32_t u;
    asm("cvt.rna.tf32.f32 %0, %1;" : "=r"(u) : "r"(fbits));
    return u;
}

__device__ __forceinline__ void cpasync16(uint32_t saddr, const void* gaddr) {
    asm volatile("cp.async.cg.shared.global [%0], [%1], 16;" :: "r"(saddr), "l"(gaddr));
}

extern __shared__ uint32_t dynsmem[];
#define AS(s, r, c) dynsmem[(s) * (2 * STAGE_WORDS) + (r) * ASTRIDE + (c)]
#define BS(s, r, c) dynsmem[(s) * (2 * STAGE_WORDS) + STAGE_WORDS + (r) * ASTRIDE + (c)]

__global__ __launch_bounds__(NTHREADS, 2)
void moe_gemm_kernel(const float* __restrict__ inputs,
                     const float* __restrict__ weight,
                     const int*   __restrict__ ssi,
                     const int*   __restrict__ offs,
                     const float* __restrict__ gates,
                     float*       __restrict__ out)
{
    __shared__ int   toks[BM];
    __shared__ float gts[BM];

    // ---- on-device grouped-GEMM tile scheduler ----
    int y = blockIdx.y;
    int e = -1, t = 0, segStart = 0, segLen = 0, cum = 0;
    #pragma unroll
    for (int i = 0; i < NEXP; i++) {
        int s   = (i == 0) ? 0 : offs[i - 1];
        int en  = offs[i];
        int len = en - s;
        int nt  = (len + BM - 1) / BM;
        if (e < 0 && y < cum + nt) { e = i; t = y - cum; segStart = s; segLen = len; }
        cum += nt;
    }
    if (e < 0) return;

    int p0 = segStart + t * BM;
    int rowsValid = segLen - t * BM;
    if (rowsValid > BM) rowsValid = BM;

    int tid = threadIdx.x;
    if (tid < BM) {
        if (tid < rowsValid) {
            int j = ssi[p0 + tid];
            toks[tid] = j >> 1;
            gts[tid]  = gates[j];
        } else {
            toks[tid] = 0;
            gts[tid]  = 0.f;
        }
    }
    __syncthreads();

    const float* W = weight + (size_t)e * D_OUT * D_IN + (size_t)(blockIdx.x * BN) * D_IN;

    int lane = tid & 31, warp = tid >> 5;
    int warpM = warp >> 1;
    int warpN = warp & 1;
    int g  = lane >> 2;
    int t4 = lane & 3;

    int lr = tid >> 3;   // 0..31 row base for async loads
    int lg = tid & 7;    // 16B group within a 32-float row

    const float* aptr[4];
    const float* bptr[4];
    #pragma unroll
    for (int i = 0; i < 4; i++) {
        int r = lr + i * 32;
        aptr[i] = inputs + (size_t)toks[r] * D_IN + lg * 4;
        bptr[i] = W + (size_t)r * D_IN + lg * 4;
    }

    float c[2][8][4];
    #pragma unroll
    for (int m = 0; m < 2; m++)
        #pragma unroll
        for (int n = 0; n < 8; n++)
            #pragma unroll
            for (int q = 0; q < 4; q++) c[m][n][q] = 0.f;

    // ---- prologue: stages 0 and 1 ----
    #pragma unroll
    for (int s = 0; s < 2; s++) {
        #pragma unroll
        for (int i = 0; i < 4; i++) {
            int r = lr + i * 32;
            cpasync16((uint32_t)__cvta_generic_to_shared(&AS(s, r, lg * 4)), aptr[i] + s * BK);
            cpasync16((uint32_t)__cvta_generic_to_shared(&BS(s, r, lg * 4)), bptr[i] + s * BK);
        }
        asm volatile("cp.async.commit_group;");
    }

    for (int kt = 0; kt < NKTILES; kt++) {
        int buf = kt % NSTAGE;
        if (kt < NKTILES - 1) asm volatile("cp.async.wait_group 1;");
        else                  asm volatile("cp.async.wait_group 0;");
        __syncthreads();
        // prefetch stage kt+2 AFTER the barrier: every warp has finished
        // computing on slot (kt+2)%3 == (kt-1)%3, so the overwrite is safe,
        // and the copies overlap this tile's MMAs.
        if (kt + 2 < NKTILES) {
            int nbuf = (kt + 2) % NSTAGE;
            int koff = (kt + 2) * BK;
            #pragma unroll
            for (int i = 0; i < 4; i++) {
                int r = lr + i * 32;
                cpasync16((uint32_t)__cvta_generic_to_shared(&AS(nbuf, r, lg * 4)), aptr[i] + koff);
                cpasync16((uint32_t)__cvta_generic_to_shared(&BS(nbuf, r, lg * 4)), bptr[i] + koff);
            }
            asm volatile("cp.async.commit_group;");
        }

        #pragma unroll
        for (int kk = 0; kk < BK; kk += 8) {
            uint32_t a[2][4], b[8][2];
            #pragma unroll
            for (int m = 0; m < 2; m++) {
                int r0 = warpM * 32 + m * 16;
                // A: rna-rounded (keeps coherent truncation bias to B side only)
                a[m][0] = f2tf32(AS(buf, r0 + g,     kk + t4));
                a[m][1] = f2tf32(AS(buf, r0 + 8 + g, kk + t4));
                a[m][2] = f2tf32(AS(buf, r0 + g,     kk + t4 + 4));
                a[m][3] = f2tf32(AS(buf, r0 + 8 + g, kk + t4 + 4));
            }
            #pragma unroll
            for (int n = 0; n < 8; n++) {
                int cb = warpN * 64 + n * 8 + g;
                // B: raw fp32 bits, HW truncates to tf32 (saves 64 cvt issues/tile)
                b[n][0] = BS(buf, cb, kk + t4);
                b[n][1] = BS(buf, cb, kk + t4 + 4);
            }
            #pragma unroll
            for (int m = 0; m < 2; m++)
                #pragma unroll
                for (int n = 0; n < 8; n++) {
                    asm volatile(
                        "mma.sync.aligned.m16n8k8.row.col.f32.tf32.tf32.f32 "
                        "{%0,%1,%2,%3},{%4,%5,%6,%7},{%8,%9},{%0,%1,%2,%3};"
                        : "+f"(c[m][n][0]), "+f"(c[m][n][1]),
                          "+f"(c[m][n][2]), "+f"(c[m][n][3])
                        : "r"(a[m][0]), "r"(a[m][1]), "r"(a[m][2]), "r"(a[m][3]),
                          "r"(b[n][0]), "r"(b[n][1]));
                }
        }
        __syncthreads();
    }

    // ---- fused gate-combine epilogue: out[token] += gate * acc ----
    int colBase = blockIdx.x * BN + warpN * 64;
    #pragma unroll
    for (int m = 0; m < 2; m++) {
        int r0 = warpM * 32 + m * 16 + g;
        int r1 = r0 + 8;
        #pragma unroll
        for (int n = 0; n < 8; n++) {
            int col = colBase + n * 8 + t4 * 2;
            if (r0 < rowsValid) {
                float w = gts[r0];
                float* o = out + (size_t)toks[r0] * D_OUT + col;
                atomicAdd(o,     w * c[m][n][0]);
                atomicAdd(o + 1, w * c[m][n][1]);
            }
            if (r1 < rowsValid) {
                float w = gts[r1];
                float* o = out + (size_t)toks[r1] * D_OUT + col;
                atomicAdd(o,     w * c[m][n][2]);
                atomicAdd(o + 1, w * c[m][n][3]);
            }
        }
    }
}

extern "C" void kernel_launch(void* const* d_in, const int* in_sizes, int n_in,
                              void* d_out, int out_size)
{
    const float* inputs = (const float*)d_in[0];
    const float* weight = (const float*)d_in[1];
    const int*   ssi    = (const int*)  d_in[n_in - 4];
    const int*   offs   = (const int*)  d_in[n_in - 2];
    const float* gates  = (const float*)d_in[n_in - 1];
    float* out = (float*)d_out;

    cudaFuncSetAttribute(moe_gemm_kernel,
                         cudaFuncAttributeMaxDynamicSharedMemorySize, SMEM_BYTES);

    zero_out_kernel<<<(N_TOK * D_OUT / 4) / 256, 256>>>((float4*)out);
    dim3 grid(D_OUT / BN, MAX_MTILES);
    moe_gemm_kernel<<<grid, NTHREADS, SMEM_BYTES>>>(inputs, weight, ssi, offs, gates, out);
}